// round 15
// baseline (speedup 1.0000x reference)
#include <cuda_runtime.h>
#include <cuda_bf16.h>
#include <cstdint>
#include <math.h>

#define N_MAX 100000
#define E_MAX 1600000

// ---------------- device scratch (static, no allocations) ----------------
__device__ __align__(256) __nv_bfloat16 g_xw1b[N_MAX * 64]; // x @ W1 (bf16)
__device__ __align__(256) __nv_bfloat16 g_h1b [N_MAX * 64]; // relu(agg(xw1)+b1) (bf16)
__device__ __align__(256) __nv_bfloat16 g_aggb[N_MAX * 64]; // agg(h1) (bf16)
__device__ __align__(256) float g_zw [N_MAX];               // fused gemm2+W3 output
__device__ __align__(256) float g_deg[N_MAX];               // dinv = rsqrt(deg)
__device__ int   g_cnt [N_MAX];                             // zero at load; prep re-zeroes
__device__ int   g_offs[N_MAX + 1];
__device__ int   g_pos [N_MAX];
__device__ int   g_esrc[E_MAX];
__device__ int   g_partial[1024];
__device__ float g_lpart[512];
__device__ int   g_lcount;                                  // zero at load; prep re-zeroes
__device__ int   g_bar_count;                               // software grid barrier state
__device__ int   g_bar_gen;

// ---------------- static streams/events (created at load, before baseline) ----------------
struct SideStream {
    cudaStream_t s1;
    cudaEvent_t  e0, e1;
    SideStream() {
        cudaStreamCreateWithFlags(&s1, cudaStreamNonBlocking);
        cudaEventCreateWithFlags(&e0, cudaEventDisableTiming);
        cudaEventCreateWithFlags(&e1, cudaEventDisableTiming);
    }
};
static SideStream g_ss;

// ---------------- helpers ----------------
__device__ __forceinline__ uint32_t smem_u32(const void* p) {
    uint32_t a;
    asm("{ .reg .u64 t; cvta.to.shared.u64 t, %1; cvt.u32.u64 %0, t; }" : "=r"(a) : "l"(p));
    return a;
}

// Sense-reversing software grid barrier. Requires all blocks co-resident.
__device__ __forceinline__ void grid_barrier(int nblk) {
    __threadfence();
    __syncthreads();
    if (threadIdx.x == 0) {
        int gen = *((volatile int*)&g_bar_gen);
        if (atomicAdd(&g_bar_count, 1) == nblk - 1) {
            g_bar_count = 0;
            __threadfence();
            atomicAdd(&g_bar_gen, 1);
        } else {
            while (*((volatile int*)&g_bar_gen) == gen) { }
        }
        __threadfence();
    }
    __syncthreads();
}

#define LDSM_X4(R0,R1,R2,R3,ADDR) \
    asm volatile("ldmatrix.sync.aligned.m8n8.x4.shared.b16 {%0,%1,%2,%3}, [%4];" \
        : "=r"(R0),"=r"(R1),"=r"(R2),"=r"(R3) : "r"(ADDR))

#define LDSM_X4T(R0,R1,R2,R3,ADDR) \
    asm volatile("ldmatrix.sync.aligned.m8n8.x4.trans.shared.b16 {%0,%1,%2,%3}, [%4];" \
        : "=r"(R0),"=r"(R1),"=r"(R2),"=r"(R3) : "r"(ADDR))

#define MMA_BF16(D,A0,A1,A2,A3,B0,B1) \
    asm volatile("mma.sync.aligned.m16n8k16.row.col.f32.bf16.bf16.f32 " \
        "{%0,%1,%2,%3}, {%4,%5,%6,%7}, {%8,%9}, {%0,%1,%2,%3};" \
        : "+f"((D)[0]),"+f"((D)[1]),"+f"((D)[2]),"+f"((D)[3]) \
        : "r"(A0),"r"(A1),"r"(A2),"r"(A3),"r"(B0),"r"(B1))

// ---------------- FUSED preprocessing: count + scan + fill in ONE kernel ----------------
// Grid must be exactly (n + 511) / 512 blocks of 512 threads (co-resident: <=196 blocks).
__global__ void __launch_bounds__(512) prep_fused(const int* __restrict__ src,
                                                  const int* __restrict__ dst,
                                                  int n, int e) {
    int t    = threadIdx.x;
    int b    = blockIdx.x;
    int nblk = gridDim.x;
    int gtid = b * 512 + t;
    int gsz  = nblk * 512;

    // phase 1: degree histogram
    for (int i = gtid; i < e; i += gsz) atomicAdd(&g_cnt[dst[i]], 1);
    grid_barrier(nblk);

    // phase 2: block sum -> partial
    __shared__ int sh[512];
    __shared__ int pre[512];
    int i = b * 512 + t;
    int orig = (i < n) ? g_cnt[i] : 0;
    sh[t] = orig;
    __syncthreads();
    for (int s = 256; s; s >>= 1) {
        if (t < s) sh[t] += sh[t + s];
        __syncthreads();
    }
    if (t == 0) g_partial[b] = sh[0];
    grid_barrier(nblk);

    // phase 3: prefix over partials + intra-block scan; restore zero-state
    pre[t] = (t < b) ? g_partial[t] : 0;
    __syncthreads();
    for (int s = 256; s; s >>= 1) {
        if (t < s) pre[t] += pre[t + s];
        __syncthreads();
    }
    int blockOff = pre[0];
    __syncthreads();
    sh[t] = orig;
    __syncthreads();
    for (int off = 1; off < 512; off <<= 1) {
        int v = (t >= off) ? sh[t - off] : 0;
        __syncthreads();
        sh[t] += v;
        __syncthreads();
    }
    if (i < n) {
        int excl = sh[t] - orig + blockOff;
        g_offs[i] = excl;
        g_pos[i]  = excl;
        g_deg[i]  = rsqrtf((float)orig + 1.0f);
        g_cnt[i]  = 0;                     // reset for next replay
    }
    if (i == 0) {
        g_offs[n] = e;
        g_lcount  = 0;                     // reset loss-finalize counter
    }
    grid_barrier(nblk);

    // phase 4: CSR fill
    for (int j = gtid; j < e; j += gsz) {
        int d = dst[j];
        int idx = atomicAdd(&g_pos[d], 1);
        g_esrc[idx] = src[j];
    }
}

// ---------------- GEMM1 (HMMA, double-buffered): xw1b = bf16(X @ W1) ----------------
#define G1_SMEM 55296

__global__ void __launch_bounds__(256) gemm1_mma(const float* __restrict__ X,
                                                 const float* __restrict__ W1, int n) {
    extern __shared__ char smem[];
    __nv_bfloat16* Abuf[2] = {(__nv_bfloat16*)(smem),         (__nv_bfloat16*)(smem + 18432)};
    __nv_bfloat16* Bbuf[2] = {(__nv_bfloat16*)(smem + 36864), (__nv_bfloat16*)(smem + 46080)};

    int tid  = threadIdx.x;
    int wid  = tid >> 5, lane = tid & 31;
    int row0 = blockIdx.x * 128;
    int wrow = wid * 16;

    uint32_t a_base[2], b_base[2];
#pragma unroll
    for (int b = 0; b < 2; b++) {
        a_base[b] = smem_u32(Abuf[b]) + (uint32_t)(wrow + (lane & 15)) * 144u + (uint32_t)(lane >> 4) * 16u;
        b_base[b] = smem_u32(Bbuf[b]) + (uint32_t)((lane & 7) + ((lane >> 3) & 1) * 8) * 144u
                                      + (uint32_t)(lane >> 4) * 16u;
    }

    int ar[8], aq[8];
    const float* aptr[8];
#pragma unroll
    for (int it = 0; it < 8; it++) {
        int f = tid + it * 256;
        ar[it] = f >> 4; aq[it] = f & 15;
        int gr = row0 + ar[it]; if (gr >= n) gr = n - 1;
        aptr[it] = X + (size_t)gr * 512 + aq[it] * 4;
    }
    int bkr[4], bq[4];
#pragma unroll
    for (int it = 0; it < 4; it++) {
        int f = tid + it * 256;
        bkr[it] = f >> 4; bq[it] = f & 15;
    }

    float4 pa[8], pb[4];
#pragma unroll
    for (int it = 0; it < 8; it++) pa[it] = *(const float4*)(aptr[it]);
#pragma unroll
    for (int it = 0; it < 4; it++) pb[it] = *(const float4*)(W1 + (size_t)bkr[it] * 64 + bq[it] * 4);

    float acc[8][4] = {};

    for (int c = 0; c < 8; c++) {
        int buf = c & 1;
        __nv_bfloat16* As = Abuf[buf];
        __nv_bfloat16* Bs = Bbuf[buf];
#pragma unroll
        for (int it = 0; it < 8; it++) {
            __nv_bfloat162 lo = __float22bfloat162_rn(make_float2(pa[it].x, pa[it].y));
            __nv_bfloat162 hi = __float22bfloat162_rn(make_float2(pa[it].z, pa[it].w));
            uint2 u; u.x = *(uint32_t*)&lo; u.y = *(uint32_t*)&hi;
            *(uint2*)(As + ar[it] * 72 + aq[it] * 4) = u;
        }
#pragma unroll
        for (int it = 0; it < 4; it++) {
            __nv_bfloat162 lo = __float22bfloat162_rn(make_float2(pb[it].x, pb[it].y));
            __nv_bfloat162 hi = __float22bfloat162_rn(make_float2(pb[it].z, pb[it].w));
            uint2 u; u.x = *(uint32_t*)&lo; u.y = *(uint32_t*)&hi;
            *(uint2*)(Bs + bkr[it] * 72 + bq[it] * 4) = u;
        }
        __syncthreads();
        if (c < 7) {
            int k0 = (c + 1) * 64;
#pragma unroll
            for (int it = 0; it < 8; it++) pa[it] = *(const float4*)(aptr[it] + k0);
#pragma unroll
            for (int it = 0; it < 4; it++)
                pb[it] = *(const float4*)(W1 + (size_t)(k0 + bkr[it]) * 64 + bq[it] * 4);
        }
#pragma unroll
        for (int ks = 0; ks < 4; ks++) {
            uint32_t a0, a1, a2, a3;
            LDSM_X4(a0, a1, a2, a3, a_base[buf] + (uint32_t)ks * 32u);
            uint32_t b[8][2];
#pragma unroll
            for (int g = 0; g < 4; g++) {
                LDSM_X4T(b[2 * g][0], b[2 * g][1], b[2 * g + 1][0], b[2 * g + 1][1],
                         b_base[buf] + (uint32_t)ks * 16u * 144u + (uint32_t)g * 32u);
            }
#pragma unroll
            for (int j = 0; j < 8; j++) MMA_BF16(acc[j], a0, a1, a2, a3, b[j][0], b[j][1]);
        }
        __syncthreads();
    }
    int rbase = row0 + wrow + (lane >> 2);
    int cbase = (lane & 3) * 2;
#pragma unroll
    for (int j = 0; j < 8; j++) {
        int col = j * 8 + cbase;
        if (rbase < n) {
            __nv_bfloat162 v = __float22bfloat162_rn(make_float2(acc[j][0], acc[j][1]));
            *(uint32_t*)(g_xw1b + (size_t)rbase * 64 + col) = *(uint32_t*)&v;
        }
        if (rbase + 8 < n) {
            __nv_bfloat162 v = __float22bfloat162_rn(make_float2(acc[j][2], acc[j][3]));
            *(uint32_t*)(g_xw1b + (size_t)(rbase + 8) * 64 + col) = *(uint32_t*)&v;
        }
    }
}

// ---------------- FUSED gathers: h1 then agg with a grid barrier between ----------------
__device__ __forceinline__ void acc_row8(float2 (&acc)[4], uint4 u, float wgt) {
    float2 v;
    v = __bfloat1622float2(*(__nv_bfloat162*)&u.x); acc[0].x += v.x * wgt; acc[0].y += v.y * wgt;
    v = __bfloat1622float2(*(((__nv_bfloat162*)&u.x) + 1)); acc[1].x += v.x * wgt; acc[1].y += v.y * wgt;
    v = __bfloat1622float2(*(__nv_bfloat162*)&u.z); acc[2].x += v.x * wgt; acc[2].y += v.y * wgt;
    v = __bfloat1622float2(*(((__nv_bfloat162*)&u.z) + 1)); acc[3].x += v.x * wgt; acc[3].y += v.y * wgt;
}

template<int EPI>  // EPI=1: relu(+bias), EPI=0: plain
__device__ __forceinline__ void gather_one(const __nv_bfloat16* __restrict__ in,
                                           __nv_bfloat16* __restrict__ out,
                                           const float* __restrict__ bias,
                                           int w, int lane) {
    int g  = lane >> 3;
    int sl = lane & 7;
    float di = g_deg[w];

    float2 acc[4] = {};
    {   // self loop (group 0 carries the weight)
        uint4 u = ((const uint4*)(in + (size_t)w * 64))[sl];
        acc_row8(acc, u, (g == 0) ? di * di : 0.f);
    }
    int p0 = g_offs[w];
    int p1 = g_offs[w + 1];
    for (int p = p0; p < p1; p += 8) {
        int  pe0 = p + g,      pe1 = p + 4 + g;
        bool ok0 = pe0 < p1,   ok1 = pe1 < p1;
        int  s0  = ok0 ? g_esrc[pe0] : w;
        int  s1  = ok1 ? g_esrc[pe1] : w;
        float w0 = ok0 ? g_deg[s0] * di : 0.f;
        float w1 = ok1 ? g_deg[s1] * di : 0.f;
        uint4 u0 = ((const uint4*)(in + (size_t)s0 * 64))[sl];
        uint4 u1 = ((const uint4*)(in + (size_t)s1 * 64))[sl];
        acc_row8(acc, u0, w0);
        acc_row8(acc, u1, w1);
    }
#pragma unroll
    for (int i = 0; i < 4; i++) {
        acc[i].x += __shfl_xor_sync(0xffffffffu, acc[i].x, 8);
        acc[i].y += __shfl_xor_sync(0xffffffffu, acc[i].y, 8);
        acc[i].x += __shfl_xor_sync(0xffffffffu, acc[i].x, 16);
        acc[i].y += __shfl_xor_sync(0xffffffffu, acc[i].y, 16);
    }
    if (lane < 8) {
        uint4 o;
        uint32_t* op = (uint32_t*)&o;
#pragma unroll
        for (int i = 0; i < 4; i++) {
            float2 v = acc[i];
            if (EPI) {
                int c = sl * 8 + i * 2;
                v.x = fmaxf(v.x + bias[c],     0.f);
                v.y = fmaxf(v.y + bias[c + 1], 0.f);
            }
            __nv_bfloat162 b = __float22bfloat162_rn(v);
            op[i] = *(uint32_t*)&b;
        }
        ((uint4*)(out + (size_t)w * 64))[sl] = o;
    }
}

#define GATH_BLOCKS 592   // co-resident: 4 blocks/SM needed, capacity >= 6

__global__ void __launch_bounds__(256, 4) gathers_fused(const float* __restrict__ bias, int n) {
    int wg     = (blockIdx.x * 256 + threadIdx.x) >> 5;
    int nwarps = gridDim.x * 8;
    int lane   = threadIdx.x & 31;

    for (int w = wg; w < n; w += nwarps)
        gather_one<1>(g_xw1b, g_h1b, bias, w, lane);
    grid_barrier(gridDim.x);
    for (int w = wg; w < n; w += nwarps)
        gather_one<0>(g_h1b, g_aggb, (const float*)nullptr, w, lane);
}

// ---------------- GEMM2 (HMMA) fused: zw[row] = relu(aggb@W2 + b2) . W3 ----------------
#define G2_SMEM 54272

__global__ void __launch_bounds__(256) gemm2_mma(const float* __restrict__ W2,
                                                 const float* __restrict__ b2,
                                                 const float* __restrict__ W3, int n) {
    extern __shared__ char smem[];
    __nv_bfloat16* As  = (__nv_bfloat16*)(smem);
    __nv_bfloat16* Bs  = (__nv_bfloat16*)(smem + 18432);
    float*         b2s = (float*)(smem + 52224);
    float*         w3s = (float*)(smem + 53248);

    int tid  = threadIdx.x;
    int wid  = tid >> 5, lane = tid & 31;
    int row0 = blockIdx.x * 128;
    int wrow = wid * 16;

#pragma unroll
    for (int it = 0; it < 8; it++) {
        int f = tid + it * 256;
        int r = f >> 4, q = f & 15;
        int gr = row0 + r; if (gr >= n) gr = n - 1;
        uint2 u = ((const uint2*)(g_aggb + (size_t)gr * 64))[q];
        *(uint2*)(As + r * 72 + q * 4) = u;
    }
#pragma unroll
    for (int it = 0; it < 16; it++) {
        int f = tid + it * 256;
        int kr = f >> 6, q = f & 63;
        float4 v = *(const float4*)(W2 + (size_t)kr * 256 + q * 4);
        __nv_bfloat162 lo = __float22bfloat162_rn(make_float2(v.x, v.y));
        __nv_bfloat162 hi = __float22bfloat162_rn(make_float2(v.z, v.w));
        uint2 u; u.x = *(uint32_t*)&lo; u.y = *(uint32_t*)&hi;
        *(uint2*)(Bs + kr * 264 + q * 4) = u;
    }
    b2s[tid] = b2[tid];
    w3s[tid] = W3[tid];
    __syncthreads();

    uint32_t abase = smem_u32(As);
    uint32_t bbase = smem_u32(Bs);
    uint32_t a_addr0 = abase + (uint32_t)(wrow + (lane & 15)) * 144u + (uint32_t)(lane >> 4) * 16u;
    uint32_t b_addr0 = bbase + (uint32_t)((lane & 7) + ((lane >> 3) & 1) * 8) * 528u
                             + (uint32_t)(lane >> 4) * 16u;

    float rs0 = 0.f, rs1 = 0.f;

#pragma unroll
    for (int cg = 0; cg < 4; cg++) {
        float acc[8][4] = {};
#pragma unroll
        for (int ks = 0; ks < 4; ks++) {
            uint32_t a0, a1, a2, a3;
            LDSM_X4(a0, a1, a2, a3, a_addr0 + (uint32_t)ks * 32u);
            uint32_t b[8][2];
#pragma unroll
            for (int g = 0; g < 4; g++) {
                LDSM_X4T(b[2 * g][0], b[2 * g][1], b[2 * g + 1][0], b[2 * g + 1][1],
                         b_addr0 + (uint32_t)ks * 16u * 528u + (uint32_t)cg * 128u + (uint32_t)g * 32u);
            }
#pragma unroll
            for (int j = 0; j < 8; j++) MMA_BF16(acc[j], a0, a1, a2, a3, b[j][0], b[j][1]);
        }
#pragma unroll
        for (int j = 0; j < 8; j++) {
            int col = cg * 64 + j * 8 + (lane & 3) * 2;
            float v;
            v = fmaxf(acc[j][0] + b2s[col],     0.f); rs0 += v * w3s[col];
            v = fmaxf(acc[j][1] + b2s[col + 1], 0.f); rs0 += v * w3s[col + 1];
            v = fmaxf(acc[j][2] + b2s[col],     0.f); rs1 += v * w3s[col];
            v = fmaxf(acc[j][3] + b2s[col + 1], 0.f); rs1 += v * w3s[col + 1];
        }
    }
    rs0 += __shfl_xor_sync(0xffffffffu, rs0, 1);
    rs0 += __shfl_xor_sync(0xffffffffu, rs0, 2);
    rs1 += __shfl_xor_sync(0xffffffffu, rs1, 1);
    rs1 += __shfl_xor_sync(0xffffffffu, rs1, 2);
    if ((lane & 3) == 0) {
        int r = row0 + wrow + (lane >> 2);
        if (r < n)     g_zw[r]     = rs0;
        if (r + 8 < n) g_zw[r + 8] = rs1;
    }
}

// ---------------- layer-3 gather + BCE + reduce (last-block finalize) ----------------
__global__ void loss_k(const float* __restrict__ y, const float* __restrict__ b3,
                       float* __restrict__ out, int n, int nblk) {
    int i = blockIdx.x * 256 + threadIdx.x;
    float l = 0.f;
    if (i < n) {
        float di = g_deg[i];
        float acc = g_zw[i] * di * di;
        int p  = g_offs[i];
        int p1 = g_offs[i + 1];
#pragma unroll 4
        for (; p < p1; p++) {
            int s = g_esrc[p];
            acc += g_zw[s] * g_deg[s] * di;
        }
        float zi = acc + b3[0];
        float yi = y[i];
        float l1p = log1pf(expf(-fabsf(zi)));
        float sp_pos = fmaxf(zi,  0.f) + l1p;
        float sp_neg = fmaxf(-zi, 0.f) + l1p;
        l = yi * sp_neg + (1.f - yi) * sp_pos;
    }
    __shared__ float sh[256];
    sh[threadIdx.x] = l;
    __syncthreads();
    for (int s = 128; s; s >>= 1) {
        if (threadIdx.x < s) sh[threadIdx.x] += sh[threadIdx.x + s];
        __syncthreads();
    }
    __shared__ bool is_last;
    if (threadIdx.x == 0) {
        g_lpart[blockIdx.x] = sh[0];
        __threadfence();
        int done = atomicAdd(&g_lcount, 1);
        is_last = (done == nblk - 1);
    }
    __syncthreads();
    if (is_last) {
        float s = 0.f;
        for (int k = threadIdx.x; k < nblk; k += 256) s += g_lpart[k];
        sh[threadIdx.x] = s;
        __syncthreads();
        for (int k = 128; k; k >>= 1) {
            if (threadIdx.x < k) sh[threadIdx.x] += sh[threadIdx.x + k];
            __syncthreads();
        }
        if (threadIdx.x == 0) out[0] = sh[0] * (1.0f / (float)n);
    }
}

// ---------------- launch ----------------
extern "C" void kernel_launch(void* const* d_in, const int* in_sizes, int n_in,
                              void* d_out, int out_size) {
    const float* x  = (const float*)d_in[0];
    const int*   ei = (const int*)  d_in[1];
    const float* y  = (const float*)d_in[2];
    const float* W1 = (const float*)d_in[3];
    const float* b1 = (const float*)d_in[4];
    const float* W2 = (const float*)d_in[5];
    const float* b2 = (const float*)d_in[6];
    const float* W3 = (const float*)d_in[7];
    const float* b3 = (const float*)d_in[8];
    float* out = (float*)d_out;

    int n = in_sizes[0] / 512;
    int e = in_sizes[1] / 2;
    const int* src = ei;
    const int* dst = ei + e;

    int nb   = (n + 511) / 512;   // prep blocks (196)
    int nbl  = (n + 255) / 256;   // loss blocks

    cudaFuncSetAttribute(gemm1_mma, cudaFuncAttributeMaxDynamicSharedMemorySize, G1_SMEM);
    cudaFuncSetAttribute(gemm2_mma, cudaFuncAttributeMaxDynamicSharedMemorySize, G2_SMEM);

    // ---- fork: GEMM1 on side stream, fused CSR preprocessing on main stream ----
    cudaEventRecord(g_ss.e0, 0);
    cudaStreamWaitEvent(g_ss.s1, g_ss.e0, 0);
    gemm1_mma<<<(n + 127) / 128, 256, G1_SMEM, g_ss.s1>>>(x, W1, n);

    prep_fused<<<nb, 512>>>(src, dst, n, e);    // count + scan + fill, 3 grid barriers

    // ---- join ----
    cudaEventRecord(g_ss.e1, g_ss.s1);
    cudaStreamWaitEvent(0, g_ss.e1, 0);

    gathers_fused<<<GATH_BLOCKS, 256>>>(b1, n); // h1 gather + barrier + agg gather
    gemm2_mma<<<(n + 127) / 128, 256, G2_SMEM>>>(W2, b2, W3, n);
    loss_k<<<nbl, 256>>>(y, b3, out, n, nbl);   // BCE + last-block finalize
}

// round 16
// speedup vs baseline: 1.2127x; 1.2127x over previous
#include <cuda_runtime.h>
#include <cuda_bf16.h>
#include <cstdint>
#include <math.h>

#define N_MAX 100000
#define E_MAX 1600000

// ---------------- device scratch (static, no allocations) ----------------
__device__ __align__(256) __nv_bfloat16 g_xw1b[N_MAX * 64]; // x @ W1 (bf16)
__device__ __align__(256) __nv_bfloat16 g_h1b [N_MAX * 64]; // relu(agg(xw1)+b1) (bf16)
__device__ __align__(256) __nv_bfloat16 g_aggb[N_MAX * 64]; // agg(h1) (bf16)
__device__ __align__(256) float g_zw [N_MAX];               // fused gemm2+W3 output
__device__ __align__(256) float g_deg[N_MAX];               // dinv = rsqrt(deg)
__device__ int   g_cnt [N_MAX];                             // zero at load; scanC re-zeroes
__device__ int   g_offs[N_MAX + 1];
__device__ int   g_pos [N_MAX];
__device__ int   g_esrc[E_MAX];
__device__ int   g_partial[1024];
__device__ float g_lpart[512];
__device__ int   g_lcount;                                  // zero at load; scanC re-zeroes

// ---------------- static streams/events (created at load, before baseline) ----------------
struct SideStream {
    cudaStream_t s1;
    cudaEvent_t  e0, e1;
    SideStream() {
        cudaStreamCreateWithFlags(&s1, cudaStreamNonBlocking);
        cudaEventCreateWithFlags(&e0, cudaEventDisableTiming);
        cudaEventCreateWithFlags(&e1, cudaEventDisableTiming);
    }
};
static SideStream g_ss;

// ---------------- helpers ----------------
__device__ __forceinline__ uint32_t smem_u32(const void* p) {
    uint32_t a;
    asm("{ .reg .u64 t; cvta.to.shared.u64 t, %1; cvt.u32.u64 %0, t; }" : "=r"(a) : "l"(p));
    return a;
}

#define LDSM_X4(R0,R1,R2,R3,ADDR) \
    asm volatile("ldmatrix.sync.aligned.m8n8.x4.shared.b16 {%0,%1,%2,%3}, [%4];" \
        : "=r"(R0),"=r"(R1),"=r"(R2),"=r"(R3) : "r"(ADDR))

#define LDSM_X4T(R0,R1,R2,R3,ADDR) \
    asm volatile("ldmatrix.sync.aligned.m8n8.x4.trans.shared.b16 {%0,%1,%2,%3}, [%4];" \
        : "=r"(R0),"=r"(R1),"=r"(R2),"=r"(R3) : "r"(ADDR))

#define MMA_BF16(D,A0,A1,A2,A3,B0,B1) \
    asm volatile("mma.sync.aligned.m16n8k16.row.col.f32.bf16.bf16.f32 " \
        "{%0,%1,%2,%3}, {%4,%5,%6,%7}, {%8,%9}, {%0,%1,%2,%3};" \
        : "+f"((D)[0]),"+f"((D)[1]),"+f"((D)[2]),"+f"((D)[3]) \
        : "r"(A0),"r"(A1),"r"(A2),"r"(A3),"r"(B0),"r"(B1))

// ---------------- preprocessing ----------------
__global__ void count_k(const int* __restrict__ dst, int e) {
    int i = blockIdx.x * blockDim.x + threadIdx.x;
    if (i < e) atomicAdd(&g_cnt[dst[i]], 1);
}

__global__ void scanA_k(int n) {
    __shared__ int sh[512];
    int i = blockIdx.x * 512 + threadIdx.x;
    sh[threadIdx.x] = (i < n) ? g_cnt[i] : 0;
    __syncthreads();
    for (int s = 256; s; s >>= 1) {
        if (threadIdx.x < s) sh[threadIdx.x] += sh[threadIdx.x + s];
        __syncthreads();
    }
    if (threadIdx.x == 0) g_partial[blockIdx.x] = sh[0];
}

// scanC: per-block prefix over partials + intra-block scan.
// Also SELF-RESTORES the zero-state: g_cnt[i]=0 after reading, g_lcount=0.
__global__ void scanC_k(int n, int e) {
    __shared__ int pre[512];
    __shared__ int sh[512];
    int t = threadIdx.x;
    pre[t] = (t < (int)blockIdx.x) ? g_partial[t] : 0;
    __syncthreads();
    for (int s = 256; s; s >>= 1) {
        if (t < s) pre[t] += pre[t + s];
        __syncthreads();
    }
    int blockOff = pre[0];

    int i = blockIdx.x * 512 + t;
    int orig = (i < n) ? g_cnt[i] : 0;
    if (i < n) g_cnt[i] = 0;                 // reset for next replay
    sh[t] = orig;
    __syncthreads();
    for (int off = 1; off < 512; off <<= 1) {
        int v = (t >= off) ? sh[t - off] : 0;
        __syncthreads();
        sh[t] += v;
        __syncthreads();
    }
    if (i < n) {
        int excl = sh[t] - orig + blockOff;
        g_offs[i] = excl;
        g_pos[i]  = excl;
        g_deg[i]  = rsqrtf((float)orig + 1.0f);
    }
    if (i == 0) {
        g_offs[n] = e;
        g_lcount  = 0;                       // reset loss-finalize counter
    }
}

__global__ void fill_k(const int* __restrict__ src, const int* __restrict__ dst, int e) {
    int i = blockIdx.x * blockDim.x + threadIdx.x;
    if (i < e) {
        int d = dst[i];
        int idx = atomicAdd(&g_pos[d], 1);
        g_esrc[idx] = src[i];
    }
}

// ---------------- GEMM1 (HMMA, double-buffered): xw1b = bf16(X @ W1) ----------------
#define G1_SMEM 55296

__global__ void __launch_bounds__(256) gemm1_mma(const float* __restrict__ X,
                                                 const float* __restrict__ W1, int n) {
    extern __shared__ char smem[];
    __nv_bfloat16* Abuf[2] = {(__nv_bfloat16*)(smem),         (__nv_bfloat16*)(smem + 18432)};
    __nv_bfloat16* Bbuf[2] = {(__nv_bfloat16*)(smem + 36864), (__nv_bfloat16*)(smem + 46080)};

    int tid  = threadIdx.x;
    int wid  = tid >> 5, lane = tid & 31;
    int row0 = blockIdx.x * 128;
    int wrow = wid * 16;

    uint32_t a_base[2], b_base[2];
#pragma unroll
    for (int b = 0; b < 2; b++) {
        a_base[b] = smem_u32(Abuf[b]) + (uint32_t)(wrow + (lane & 15)) * 144u + (uint32_t)(lane >> 4) * 16u;
        b_base[b] = smem_u32(Bbuf[b]) + (uint32_t)((lane & 7) + ((lane >> 3) & 1) * 8) * 144u
                                      + (uint32_t)(lane >> 4) * 16u;
    }

    int ar[8], aq[8];
    const float* aptr[8];
#pragma unroll
    for (int it = 0; it < 8; it++) {
        int f = tid + it * 256;
        ar[it] = f >> 4; aq[it] = f & 15;
        int gr = row0 + ar[it]; if (gr >= n) gr = n - 1;
        aptr[it] = X + (size_t)gr * 512 + aq[it] * 4;
    }
    int bkr[4], bq[4];
#pragma unroll
    for (int it = 0; it < 4; it++) {
        int f = tid + it * 256;
        bkr[it] = f >> 4; bq[it] = f & 15;
    }

    float4 pa[8], pb[4];
#pragma unroll
    for (int it = 0; it < 8; it++) pa[it] = *(const float4*)(aptr[it]);
#pragma unroll
    for (int it = 0; it < 4; it++) pb[it] = *(const float4*)(W1 + (size_t)bkr[it] * 64 + bq[it] * 4);

    float acc[8][4] = {};

    for (int c = 0; c < 8; c++) {
        int buf = c & 1;
        __nv_bfloat16* As = Abuf[buf];
        __nv_bfloat16* Bs = Bbuf[buf];
#pragma unroll
        for (int it = 0; it < 8; it++) {
            __nv_bfloat162 lo = __float22bfloat162_rn(make_float2(pa[it].x, pa[it].y));
            __nv_bfloat162 hi = __float22bfloat162_rn(make_float2(pa[it].z, pa[it].w));
            uint2 u; u.x = *(uint32_t*)&lo; u.y = *(uint32_t*)&hi;
            *(uint2*)(As + ar[it] * 72 + aq[it] * 4) = u;
        }
#pragma unroll
        for (int it = 0; it < 4; it++) {
            __nv_bfloat162 lo = __float22bfloat162_rn(make_float2(pb[it].x, pb[it].y));
            __nv_bfloat162 hi = __float22bfloat162_rn(make_float2(pb[it].z, pb[it].w));
            uint2 u; u.x = *(uint32_t*)&lo; u.y = *(uint32_t*)&hi;
            *(uint2*)(Bs + bkr[it] * 72 + bq[it] * 4) = u;
        }
        __syncthreads();
        if (c < 7) {
            int k0 = (c + 1) * 64;
#pragma unroll
            for (int it = 0; it < 8; it++) pa[it] = *(const float4*)(aptr[it] + k0);
#pragma unroll
            for (int it = 0; it < 4; it++)
                pb[it] = *(const float4*)(W1 + (size_t)(k0 + bkr[it]) * 64 + bq[it] * 4);
        }
#pragma unroll
        for (int ks = 0; ks < 4; ks++) {
            uint32_t a0, a1, a2, a3;
            LDSM_X4(a0, a1, a2, a3, a_base[buf] + (uint32_t)ks * 32u);
            uint32_t b[8][2];
#pragma unroll
            for (int g = 0; g < 4; g++) {
                LDSM_X4T(b[2 * g][0], b[2 * g][1], b[2 * g + 1][0], b[2 * g + 1][1],
                         b_base[buf] + (uint32_t)ks * 16u * 144u + (uint32_t)g * 32u);
            }
#pragma unroll
            for (int j = 0; j < 8; j++) MMA_BF16(acc[j], a0, a1, a2, a3, b[j][0], b[j][1]);
        }
        __syncthreads();
    }
    int rbase = row0 + wrow + (lane >> 2);
    int cbase = (lane & 3) * 2;
#pragma unroll
    for (int j = 0; j < 8; j++) {
        int col = j * 8 + cbase;
        if (rbase < n) {
            __nv_bfloat162 v = __float22bfloat162_rn(make_float2(acc[j][0], acc[j][1]));
            *(uint32_t*)(g_xw1b + (size_t)rbase * 64 + col) = *(uint32_t*)&v;
        }
        if (rbase + 8 < n) {
            __nv_bfloat162 v = __float22bfloat162_rn(make_float2(acc[j][2], acc[j][3]));
            *(uint32_t*)(g_xw1b + (size_t)(rbase + 8) * 64 + col) = *(uint32_t*)&v;
        }
    }
}

// ---------------- MLP-8 gathers: warp per node, 8 edges in flight ----------------
__device__ __forceinline__ void acc_row8(float2 (&acc)[4], uint4 u, float wgt) {
    float2 v;
    v = __bfloat1622float2(*(__nv_bfloat162*)&u.x); acc[0].x += v.x * wgt; acc[0].y += v.y * wgt;
    v = __bfloat1622float2(*(((__nv_bfloat162*)&u.x) + 1)); acc[1].x += v.x * wgt; acc[1].y += v.y * wgt;
    v = __bfloat1622float2(*(__nv_bfloat162*)&u.z); acc[2].x += v.x * wgt; acc[2].y += v.y * wgt;
    v = __bfloat1622float2(*(((__nv_bfloat162*)&u.z) + 1)); acc[3].x += v.x * wgt; acc[3].y += v.y * wgt;
}

template<int EPI>  // EPI=1: relu(+bias), EPI=0: plain
__device__ __forceinline__ void gather64(const __nv_bfloat16* __restrict__ in,
                                         __nv_bfloat16* __restrict__ out,
                                         const float* __restrict__ bias, int n) {
    int w    = (blockIdx.x * blockDim.x + threadIdx.x) >> 5;
    int lane = threadIdx.x & 31;
    if (w >= n) return;
    int g  = lane >> 3;
    int sl = lane & 7;
    float di = g_deg[w];

    float2 acc[4] = {};
    {   // self loop (group 0 carries the weight)
        uint4 u = ((const uint4*)(in + (size_t)w * 64))[sl];
        acc_row8(acc, u, (g == 0) ? di * di : 0.f);
    }
    int p0 = g_offs[w];
    int p1 = g_offs[w + 1];
    for (int p = p0; p < p1; p += 8) {
        int  pe0 = p + g,      pe1 = p + 4 + g;
        bool ok0 = pe0 < p1,   ok1 = pe1 < p1;
        int  s0  = ok0 ? g_esrc[pe0] : w;
        int  s1  = ok1 ? g_esrc[pe1] : w;
        float w0 = ok0 ? g_deg[s0] * di : 0.f;
        float w1 = ok1 ? g_deg[s1] * di : 0.f;
        uint4 u0 = ((const uint4*)(in + (size_t)s0 * 64))[sl];
        uint4 u1 = ((const uint4*)(in + (size_t)s1 * 64))[sl];
        acc_row8(acc, u0, w0);
        acc_row8(acc, u1, w1);
    }
#pragma unroll
    for (int i = 0; i < 4; i++) {
        acc[i].x += __shfl_xor_sync(0xffffffffu, acc[i].x, 8);
        acc[i].y += __shfl_xor_sync(0xffffffffu, acc[i].y, 8);
        acc[i].x += __shfl_xor_sync(0xffffffffu, acc[i].x, 16);
        acc[i].y += __shfl_xor_sync(0xffffffffu, acc[i].y, 16);
    }
    if (lane < 8) {
        uint4 o;
        uint32_t* op = (uint32_t*)&o;
#pragma unroll
        for (int i = 0; i < 4; i++) {
            float2 v = acc[i];
            if (EPI) {
                int c = sl * 8 + i * 2;
                v.x = fmaxf(v.x + bias[c],     0.f);
                v.y = fmaxf(v.y + bias[c + 1], 0.f);
            }
            __nv_bfloat162 b = __float22bfloat162_rn(v);
            op[i] = *(uint32_t*)&b;
        }
        ((uint4*)(out + (size_t)w * 64))[sl] = o;
    }
}

__global__ void gather_h1(const float* __restrict__ bias, int n) {
    gather64<1>(g_xw1b, g_h1b, bias, n);
}
__global__ void gather_agg(int n) {
    gather64<0>(g_h1b, g_aggb, (const float*)nullptr, n);
}

// ---------------- GEMM2 (HMMA) fused, 2 row-tiles per CTA ----------------
// zw[row] = relu(aggb@W2 + b2) . W3 ; B (W2) staged ONCE, reused for both tiles.
#define G2_SMEM 54272

__global__ void __launch_bounds__(256) gemm2_mma(const float* __restrict__ W2,
                                                 const float* __restrict__ b2,
                                                 const float* __restrict__ W3, int n) {
    extern __shared__ char smem[];
    __nv_bfloat16* As  = (__nv_bfloat16*)(smem);
    __nv_bfloat16* Bs  = (__nv_bfloat16*)(smem + 18432);
    float*         b2s = (float*)(smem + 52224);
    float*         w3s = (float*)(smem + 53248);

    int tid  = threadIdx.x;
    int wid  = tid >> 5, lane = tid & 31;
    int wrow = wid * 16;

    // stage B (W2) once: 64x256 f32 -> bf16
#pragma unroll
    for (int it = 0; it < 16; it++) {
        int f = tid + it * 256;
        int kr = f >> 6, q = f & 63;
        float4 v = *(const float4*)(W2 + (size_t)kr * 256 + q * 4);
        __nv_bfloat162 lo = __float22bfloat162_rn(make_float2(v.x, v.y));
        __nv_bfloat162 hi = __float22bfloat162_rn(make_float2(v.z, v.w));
        uint2 u; u.x = *(uint32_t*)&lo; u.y = *(uint32_t*)&hi;
        *(uint2*)(Bs + kr * 264 + q * 4) = u;
    }
    b2s[tid] = b2[tid];
    w3s[tid] = W3[tid];

    uint32_t abase = smem_u32(As);
    uint32_t bbase = smem_u32(Bs);
    uint32_t a_addr0 = abase + (uint32_t)(wrow + (lane & 15)) * 144u + (uint32_t)(lane >> 4) * 16u;
    uint32_t b_addr0 = bbase + (uint32_t)((lane & 7) + ((lane >> 3) & 1) * 8) * 528u
                             + (uint32_t)(lane >> 4) * 16u;

#pragma unroll
    for (int t2 = 0; t2 < 2; t2++) {
        int row0 = (blockIdx.x * 2 + t2) * 128;
        if (row0 >= n) break;

        // stage A for this tile (sync guards both B-visibility on t2=0 and
        // prior-iteration LDSM completion on t2=1)
#pragma unroll
        for (int it = 0; it < 8; it++) {
            int f = tid + it * 256;
            int r = f >> 4, q = f & 15;
            int gr = row0 + r; if (gr >= n) gr = n - 1;
            uint2 u = ((const uint2*)(g_aggb + (size_t)gr * 64))[q];
            *(uint2*)(As + r * 72 + q * 4) = u;
        }
        __syncthreads();

        float rs0 = 0.f, rs1 = 0.f;
#pragma unroll
        for (int cg = 0; cg < 4; cg++) {
            float acc[8][4] = {};
#pragma unroll
            for (int ks = 0; ks < 4; ks++) {
                uint32_t a0, a1, a2, a3;
                LDSM_X4(a0, a1, a2, a3, a_addr0 + (uint32_t)ks * 32u);
                uint32_t b[8][2];
#pragma unroll
                for (int g = 0; g < 4; g++) {
                    LDSM_X4T(b[2 * g][0], b[2 * g][1], b[2 * g + 1][0], b[2 * g + 1][1],
                             b_addr0 + (uint32_t)ks * 16u * 528u + (uint32_t)cg * 128u + (uint32_t)g * 32u);
                }
#pragma unroll
                for (int j = 0; j < 8; j++) MMA_BF16(acc[j], a0, a1, a2, a3, b[j][0], b[j][1]);
            }
#pragma unroll
            for (int j = 0; j < 8; j++) {
                int col = cg * 64 + j * 8 + (lane & 3) * 2;
                float v;
                v = fmaxf(acc[j][0] + b2s[col],     0.f); rs0 += v * w3s[col];
                v = fmaxf(acc[j][1] + b2s[col + 1], 0.f); rs0 += v * w3s[col + 1];
                v = fmaxf(acc[j][2] + b2s[col],     0.f); rs1 += v * w3s[col];
                v = fmaxf(acc[j][3] + b2s[col + 1], 0.f); rs1 += v * w3s[col + 1];
            }
        }
        rs0 += __shfl_xor_sync(0xffffffffu, rs0, 1);
        rs0 += __shfl_xor_sync(0xffffffffu, rs0, 2);
        rs1 += __shfl_xor_sync(0xffffffffu, rs1, 1);
        rs1 += __shfl_xor_sync(0xffffffffu, rs1, 2);
        if ((lane & 3) == 0) {
            int r = row0 + wrow + (lane >> 2);
            if (r < n)     g_zw[r]     = rs0;
            if (r + 8 < n) g_zw[r + 8] = rs1;
        }
        __syncthreads();   // all LDSM reads done before next A restage
    }
}

// ---------------- layer-3 gather + BCE + reduce (last-block finalize) ----------------
__global__ void loss_k(const float* __restrict__ y, const float* __restrict__ b3,
                       float* __restrict__ out, int n, int nblk) {
    int i = blockIdx.x * 256 + threadIdx.x;
    float l = 0.f;
    if (i < n) {
        float di = g_deg[i];
        float acc = g_zw[i] * di * di;
        int p  = g_offs[i];
        int p1 = g_offs[i + 1];
#pragma unroll 4
        for (; p < p1; p++) {
            int s = g_esrc[p];
            acc += g_zw[s] * g_deg[s] * di;
        }
        float zi = acc + b3[0];
        float yi = y[i];
        float l1p = log1pf(expf(-fabsf(zi)));
        float sp_pos = fmaxf(zi,  0.f) + l1p;
        float sp_neg = fmaxf(-zi, 0.f) + l1p;
        l = yi * sp_neg + (1.f - yi) * sp_pos;
    }
    __shared__ float sh[256];
    sh[threadIdx.x] = l;
    __syncthreads();
    for (int s = 128; s; s >>= 1) {
        if (threadIdx.x < s) sh[threadIdx.x] += sh[threadIdx.x + s];
        __syncthreads();
    }
    __shared__ bool is_last;
    if (threadIdx.x == 0) {
        g_lpart[blockIdx.x] = sh[0];
        __threadfence();
        int done = atomicAdd(&g_lcount, 1);
        is_last = (done == nblk - 1);
    }
    __syncthreads();
    if (is_last) {
        float s = 0.f;
        for (int k = threadIdx.x; k < nblk; k += 256) s += g_lpart[k];
        sh[threadIdx.x] = s;
        __syncthreads();
        for (int k = 128; k; k >>= 1) {
            if (threadIdx.x < k) sh[threadIdx.x] += sh[threadIdx.x + k];
            __syncthreads();
        }
        if (threadIdx.x == 0) out[0] = sh[0] * (1.0f / (float)n);
    }
}

// ---------------- launch ----------------
extern "C" void kernel_launch(void* const* d_in, const int* in_sizes, int n_in,
                              void* d_out, int out_size) {
    const float* x  = (const float*)d_in[0];
    const int*   ei = (const int*)  d_in[1];
    const float* y  = (const float*)d_in[2];
    const float* W1 = (const float*)d_in[3];
    const float* b1 = (const float*)d_in[4];
    const float* W2 = (const float*)d_in[5];
    const float* b2 = (const float*)d_in[6];
    const float* W3 = (const float*)d_in[7];
    const float* b3 = (const float*)d_in[8];
    float* out = (float*)d_out;

    int n = in_sizes[0] / 512;
    int e = in_sizes[1] / 2;
    const int* src = ei;
    const int* dst = ei + e;

    int nb   = (n + 511) / 512;   // scan blocks
    int nbl  = (n + 255) / 256;   // loss blocks

    cudaFuncSetAttribute(gemm1_mma, cudaFuncAttributeMaxDynamicSharedMemorySize, G1_SMEM);
    cudaFuncSetAttribute(gemm2_mma, cudaFuncAttributeMaxDynamicSharedMemorySize, G2_SMEM);

    // ---- fork: GEMM1 on side stream, CSR preprocessing on main stream ----
    cudaEventRecord(g_ss.e0, 0);
    cudaStreamWaitEvent(g_ss.s1, g_ss.e0, 0);
    gemm1_mma<<<(n + 127) / 128, 256, G1_SMEM, g_ss.s1>>>(x, W1, n);

    count_k<<<(e + 255) / 256, 256>>>(dst, e);    // g_cnt zero (load-time / scanC restore)
    scanA_k<<<nb, 512>>>(n);
    scanC_k<<<nb, 512>>>(n, e);                   // also re-zeroes g_cnt + g_lcount
    fill_k <<<(e + 255) / 256, 256>>>(src, dst, e);

    // ---- join ----
    cudaEventRecord(g_ss.e1, g_ss.s1);
    cudaStreamWaitEvent(0, g_ss.e1, 0);

    gather_h1 <<<(n + 7) / 8, 256>>>(b1, n);      // h1b = bf16(relu(A xw1 + b1))
    gather_agg<<<(n + 7) / 8, 256>>>(n);          // aggb = bf16(A h1)
    gemm2_mma<<<(n + 255) / 256, 256, G2_SMEM>>>(W2, b2, W3, n);  // 2 tiles/CTA
    loss_k<<<nbl, 256>>>(y, b3, out, n, nbl);     // BCE + last-block finalize
}